// round 7
// baseline (speedup 1.0000x reference)
#include <cuda_runtime.h>
#include <cuda_bf16.h>
#include <cstdint>

#define S_LEN 2048
#define HID   4096
#define NH    32
#define NKV   8
#define HD    128
#define KVD   (NKV*HD)   /* 1024 */
#define QD    (NH*HD)    /* 4096 */
#define WROWS (QD+2*KVD) /* 6144 */
#define ATT_SCALE 0.08838834764831845f

// ---------------------------------------------------------------------------
// Scratch (device globals; no runtime allocation allowed)
// ---------------------------------------------------------------------------
__device__ float g_Q [S_LEN*QD];   // Q projection, RoPE'd in place (fp32)
__device__ float g_K [S_LEN*KVD];  // K projection, RoPE'd in place (fp32)
__device__ float g_V [S_LEN*KVD];

// bf16 split operands (x = hi + lo)
__device__ __nv_bfloat16 g_hsH[S_LEN*HID], g_hsL[S_LEN*HID];
__device__ __nv_bfloat16 g_WH [WROWS*HID], g_WL [WROWS*HID];   // wq|wk|wv stacked
__device__ __nv_bfloat16 g_WOH[HID*QD],    g_WOL[HID*QD];
__device__ __nv_bfloat16 g_AOH[S_LEN*QD],  g_AOL[S_LEN*QD];
// split Q/K/V for HMMA flash (post-RoPE)
__device__ __nv_bfloat16 g_QH[S_LEN*QD],  g_QL[S_LEN*QD];
__device__ __nv_bfloat16 g_KH[S_LEN*KVD], g_KL[S_LEN*KVD];
__device__ __nv_bfloat16 g_VH[S_LEN*KVD], g_VL[S_LEN*KVD];

// ---------------------------------------------------------------------------
// mma.sync helpers (sm_80-level, compiles for compute_103)
// ---------------------------------------------------------------------------
__device__ __forceinline__ uint32_t smem_u32(const void* p) {
    uint32_t a;
    asm("{ .reg .u64 t; cvta.to.shared.u64 t, %1; cvt.u32.u64 %0, t; }"
        : "=r"(a) : "l"(p));
    return a;
}

__device__ __forceinline__ void ldsm_x4(uint32_t* r, uint32_t addr) {
    asm volatile("ldmatrix.sync.aligned.m8n8.x4.shared.b16 {%0,%1,%2,%3}, [%4];"
        : "=r"(r[0]), "=r"(r[1]), "=r"(r[2]), "=r"(r[3]) : "r"(addr));
}

__device__ __forceinline__ void ldsm_x4_t(uint32_t* r, uint32_t addr) {
    asm volatile("ldmatrix.sync.aligned.m8n8.x4.trans.shared.b16 {%0,%1,%2,%3}, [%4];"
        : "=r"(r[0]), "=r"(r[1]), "=r"(r[2]), "=r"(r[3]) : "r"(addr));
}

__device__ __forceinline__ void mma16816(float* d, const uint32_t* a,
                                         const uint32_t* b) {
    asm volatile(
        "mma.sync.aligned.m16n8k16.row.col.f32.bf16.bf16.f32 "
        "{%0,%1,%2,%3},{%4,%5,%6,%7},{%8,%9},{%0,%1,%2,%3};"
        : "+f"(d[0]), "+f"(d[1]), "+f"(d[2]), "+f"(d[3])
        : "r"(a[0]), "r"(a[1]), "r"(a[2]), "r"(a[3]), "r"(b[0]), "r"(b[1]));
}

__device__ __forceinline__ void cp16(uint32_t saddr, const void* g) {
    asm volatile("cp.async.cg.shared.global [%0], [%1], 16;"
        :: "r"(saddr), "l"(g) : "memory");
}

#define CP_COMMIT() asm volatile("cp.async.commit_group;" ::: "memory")
#define CP_WAIT(n)  asm volatile("cp.async.wait_group %0;" :: "n"(n) : "memory")

// pack two f32 -> bf16x2 (lo first)
__device__ __forceinline__ uint32_t pack_bf(float lo, float hi) {
    uint32_t r;
    asm("cvt.rn.bf16x2.f32 %0, %1, %2;" : "=r"(r) : "f"(hi), "f"(lo));
    return r;
}

// ---------------------------------------------------------------------------
// Split-bf16 HMMA GEMM: C[128,128] = (Ah+Al)[128,K] @ (Bh+Bl)[128,K]^T
// 256 threads, warp grid 2(m) x 4(n), warp tile 64x32. BK=32, double buffered.
// __launch_bounds__(256, 2): cap regs at 128 -> 2 CTAs/SM (smem 2x80KB fits).
// ---------------------------------------------------------------------------
#define LDT      40
#define TILE_B   (128*LDT*2)
#define STAGE_B  (4*TILE_B)
#define GEMM_SMEM (2*STAGE_B)

__device__ __forceinline__ void mma_gemm(
    const __nv_bfloat16* __restrict__ pAh, const __nv_bfloat16* __restrict__ pAl,
    const __nv_bfloat16* __restrict__ pBh, const __nv_bfloat16* __restrict__ pBl,
    int K, float* __restrict__ Cp, int ldc)
{
    extern __shared__ char smc[];
    const uint32_t smb = smem_u32(smc);
    const int tid = threadIdx.x;
    const int wid = tid >> 5;
    const int l   = tid & 31;
    const int wm  = wid & 1;
    const int wn  = wid >> 1;

    float acc[4][4][4] = {};
    const int nk = K >> 5;

#define ISSUE_STAGE(s, kb) do {                                              \
        uint32_t sb_ = smb + (s) * STAGE_B;                                  \
        _Pragma("unroll")                                                    \
        for (int t = 0; t < 8; t++) {                                        \
            const int tile = t >> 1;                                         \
            int idx2 = tid + (t & 1) * 256;                                  \
            int row  = idx2 >> 2;                                            \
            int ch   = idx2 & 3;                                             \
            const __nv_bfloat16* src =                                       \
                (tile == 0) ? pAh : (tile == 1) ? pAl :                      \
                (tile == 2) ? pBh : pBl;                                     \
            cp16(sb_ + tile * TILE_B + (row * LDT + ch * 8) * 2,             \
                 src + (size_t)row * K + (kb) + ch * 8);                     \
        }                                                                    \
        CP_COMMIT();                                                         \
    } while (0)

    ISSUE_STAGE(0, 0);

    for (int kt = 0; kt < nk; kt++) {
        const int s = kt & 1;
        if (kt + 1 < nk) {
            ISSUE_STAGE(s ^ 1, (kt + 1) << 5);
            CP_WAIT(1);
        } else {
            CP_WAIT(0);
        }
        __syncthreads();

        const uint32_t sb  = smb + s * STAGE_B;
        const uint32_t aAh = sb;
        const uint32_t aAl = sb + TILE_B;
        const uint32_t aBh = sb + 2 * TILE_B;
        const uint32_t aBl = sb + 3 * TILE_B;

#pragma unroll
        for (int ks = 0; ks < 2; ks++) {
            const int k0 = ks * 16;
            uint32_t ah[4][4], al[4][4], bh[2][4], bl[2][4];
#pragma unroll
            for (int mt = 0; mt < 4; mt++) {
                uint32_t off = (uint32_t)((wm * 64 + mt * 16 + (l & 15)) * LDT
                                          + k0 + 8 * (l >> 4)) * 2;
                ldsm_x4(ah[mt], aAh + off);
                ldsm_x4(al[mt], aAl + off);
            }
#pragma unroll
            for (int p = 0; p < 2; p++) {
                uint32_t off = (uint32_t)((wn * 32 + p * 16 + 8 * (l >> 4) + (l & 7)) * LDT
                                          + k0 + 8 * ((l >> 3) & 1)) * 2;
                ldsm_x4(bh[p], aBh + off);
                ldsm_x4(bl[p], aBl + off);
            }
#pragma unroll
            for (int mt = 0; mt < 4; mt++)
#pragma unroll
                for (int nt = 0; nt < 4; nt++) {
                    const uint32_t* Bh_ = &bh[nt >> 1][(nt & 1) * 2];
                    const uint32_t* Bl_ = &bl[nt >> 1][(nt & 1) * 2];
                    mma16816(acc[mt][nt], ah[mt], Bh_);
                    mma16816(acc[mt][nt], ah[mt], Bl_);
                    mma16816(acc[mt][nt], al[mt], Bh_);
                }
        }
        __syncthreads();
    }

    const int m_base = wm * 64;
    const int n_base = wn * 32;
#pragma unroll
    for (int mt = 0; mt < 4; mt++)
#pragma unroll
        for (int nt = 0; nt < 4; nt++) {
            int row = m_base + mt * 16 + (l >> 2);
            int col = n_base + nt * 8 + 2 * (l & 3);
            float2 v0 = {acc[mt][nt][0], acc[mt][nt][1]};
            float2 v1 = {acc[mt][nt][2], acc[mt][nt][3]};
            *(float2*)(Cp + (size_t)row * ldc + col)       = v0;
            *(float2*)(Cp + (size_t)(row + 8) * ldc + col) = v1;
        }
#undef ISSUE_STAGE
}

__global__ void __launch_bounds__(256, 2) qkv_mma_kernel()
{
    const int bx = blockIdx.x;
    const int m0 = blockIdx.y * 128;
    float* C; int ldc, n0;
    if (bx < 32)      { C = g_Q; ldc = QD;  n0 = bx << 7; }
    else if (bx < 40) { C = g_K; ldc = KVD; n0 = (bx - 32) << 7; }
    else              { C = g_V; ldc = KVD; n0 = (bx - 40) << 7; }
    mma_gemm(g_hsH + (size_t)m0 * HID, g_hsL + (size_t)m0 * HID,
             g_WH  + (size_t)(bx << 7) * HID, g_WL + (size_t)(bx << 7) * HID,
             HID, C + (size_t)m0 * ldc + n0, ldc);
}

__global__ void __launch_bounds__(256, 2) o_mma_kernel(float* __restrict__ out)
{
    const int m0 = blockIdx.y * 128;
    const int n0 = blockIdx.x * 128;
    mma_gemm(g_AOH + (size_t)m0 * QD, g_AOL + (size_t)m0 * QD,
             g_WOH + (size_t)n0 * QD, g_WOL + (size_t)n0 * QD,
             QD, out + (size_t)m0 * HID + n0, HID);
}

// ---------------------------------------------------------------------------
// fp32 -> bf16 hi/lo split (dst selected device-side; never pass __device__
// symbols from host — ATS makes the GPU silently write host RAM).
// ---------------------------------------------------------------------------
__device__ __forceinline__ void cvt4(const float* __restrict__ src,
                                     __nv_bfloat16* __restrict__ hi,
                                     __nv_bfloat16* __restrict__ lo, int i)
{
    float4 x = *(const float4*)(src + i);
    __nv_bfloat16 h0 = __float2bfloat16(x.x);
    __nv_bfloat16 h1 = __float2bfloat16(x.y);
    __nv_bfloat16 h2 = __float2bfloat16(x.z);
    __nv_bfloat16 h3 = __float2bfloat16(x.w);
    __nv_bfloat16 l0 = __float2bfloat16(x.x - __bfloat162float(h0));
    __nv_bfloat16 l1 = __float2bfloat16(x.y - __bfloat162float(h1));
    __nv_bfloat16 l2 = __float2bfloat16(x.z - __bfloat162float(h2));
    __nv_bfloat16 l3 = __float2bfloat16(x.w - __bfloat162float(h3));
    __nv_bfloat162 hv0{h0, h1}, hv1{h2, h3}, lv0{l0, l1}, lv1{l2, l3};
    *(__nv_bfloat162*)(hi + i)     = hv0;
    *(__nv_bfloat162*)(hi + i + 2) = hv1;
    *(__nv_bfloat162*)(lo + i)     = lv0;
    *(__nv_bfloat162*)(lo + i + 2) = lv1;
}

__global__ void cvt_sel_kernel(const float* __restrict__ src, int which,
                               size_t off, int n)
{
    int i = (blockIdx.x * blockDim.x + threadIdx.x) << 2;
    if (i >= n) return;
    __nv_bfloat16 *hi, *lo;
    if (which == 0)      { hi = g_hsH;      lo = g_hsL;      }
    else if (which == 1) { hi = g_WH + off; lo = g_WL + off; }
    else                 { hi = g_WOH;      lo = g_WOL;      }
    cvt4(src, hi, lo, i);
}

// Q/K/V fp32 -> split bf16 (post-RoPE)
__global__ void cvt_qkv_kernel()
{
    int i = (blockIdx.x * blockDim.x + threadIdx.x) << 2;
    const int nq = S_LEN * QD;
    const int nk = S_LEN * KVD;
    if (i < nq)               cvt4(g_Q, g_QH, g_QL, i);
    else if (i < nq + nk)     cvt4(g_K, g_KH, g_KL, i - nq);
    else if (i < nq + 2 * nk) cvt4(g_V, g_VH, g_VL, i - nq - nk);
}

// ---------------------------------------------------------------------------
// RoPE (rotate-half), in place on g_Q and g_K (fp32).
// ---------------------------------------------------------------------------
__global__ void rope_kernel(const float* __restrict__ cosb,
                            const float* __restrict__ sinb)
{
    int idx = blockIdx.x * blockDim.x + threadIdx.x;
    const int qtot = S_LEN * NH * 64;
    const int ktot = S_LEN * NKV * 64;
    if (idx < qtot) {
        int d = idx & 63;
        int h = (idx >> 6) & 31;
        int s = idx >> 11;
        float c  = cosb[s * HD + d];
        float sn = sinb[s * HD + d];
        float* base = g_Q + (size_t)s * QD + h * HD;
        float x1 = base[d], x2 = base[d + 64];
        base[d]      = x1 * c - x2 * sn;
        base[d + 64] = x2 * c + x1 * sn;
    } else if (idx < qtot + ktot) {
        int j = idx - qtot;
        int d = j & 63;
        int h = (j >> 6) & 7;
        int s = j >> 9;
        float c  = cosb[s * HD + d];
        float sn = sinb[s * HD + d];
        float* base = g_K + (size_t)s * KVD + h * HD;
        float x1 = base[d], x2 = base[d + 64];
        base[d]      = x1 * c - x2 * sn;
        base[d + 64] = x2 * c + x1 * sn;
    }
}

// ---------------------------------------------------------------------------
// HMMA causal flash attention (split-bf16, 3-pass for QK and PV).
// Pipelined: K(j+1) issued after QK(j); V(j+1) issued after PV(j).
// In-order cp.async group retirement guarantees wait_group(1) semantics.
// Writes split-bf16 AO directly (no fp32 round-trip).
// ---------------------------------------------------------------------------
#define LDF 136
#define FTILE (64*LDF*2)            /* 17408 B */
#define FLASH_SMEM (6*FTILE)        /* 104448 B -> 2 CTAs/SM */

__global__ void __launch_bounds__(128) flash_mma_kernel()
{
    extern __shared__ char fsm[];
    const uint32_t smb = smem_u32(fsm);
    const int tid = threadIdx.x;
    const int w   = tid >> 5;
    const int l   = tid & 31;
    const int qt  = 31 - (int)blockIdx.x;
    const int h   = blockIdx.y;
    const int kvh = h >> 2;

    const uint32_t sQH = smb;
    const uint32_t sQL = smb + FTILE;
    const uint32_t sKH = smb + 2 * FTILE;
    const uint32_t sKL = smb + 3 * FTILE;
    const uint32_t sVH = smb + 4 * FTILE;
    const uint32_t sVL = smb + 5 * FTILE;

#define LOAD_K(jt_) do {                                                     \
        const size_t kb_ = (size_t)((jt_) * 64) * KVD + kvh * HD;            \
        _Pragma("unroll")                                                    \
        for (int t = 0; t < 8; t++) {                                        \
            int idx = tid + t * 128;                                         \
            int row = idx >> 4, c8 = (idx & 15) << 3;                        \
            uint32_t doff = (uint32_t)(row * LDF + c8) * 2;                  \
            size_t gs = kb_ + (size_t)row * KVD + c8;                        \
            cp16(sKH + doff, g_KH + gs);                                     \
            cp16(sKL + doff, g_KL + gs);                                     \
        }                                                                    \
        CP_COMMIT();                                                         \
    } while (0)

#define LOAD_V(jt_) do {                                                     \
        const size_t kb_ = (size_t)((jt_) * 64) * KVD + kvh * HD;            \
        _Pragma("unroll")                                                    \
        for (int t = 0; t < 8; t++) {                                        \
            int idx = tid + t * 128;                                         \
            int row = idx >> 4, c8 = (idx & 15) << 3;                        \
            uint32_t doff = (uint32_t)(row * LDF + c8) * 2;                  \
            size_t gs = kb_ + (size_t)row * KVD + c8;                        \
            cp16(sVH + doff, g_VH + gs);                                     \
            cp16(sVL + doff, g_VL + gs);                                     \
        }                                                                    \
        CP_COMMIT();                                                         \
    } while (0)

    // Load Q tile (group 0), then K(0) (group 1), V(0) (group 2).
    {
        const size_t qbase = (size_t)(qt * 64) * QD + h * HD;
#pragma unroll
        for (int t = 0; t < 8; t++) {
            int idx = tid + t * 128;
            int row = idx >> 4, c8 = (idx & 15) << 3;
            uint32_t doff = (uint32_t)(row * LDF + c8) * 2;
            cp16(sQH + doff, g_QH + qbase + (size_t)row * QD + c8);
            cp16(sQL + doff, g_QL + qbase + (size_t)row * QD + c8);
        }
        CP_COMMIT();
    }
    LOAD_K(0);
    LOAD_V(0);

    float S[8][4];
    float O[16][4] = {};
    float m0 = -1e30f, m1 = -1e30f, lr0 = 0.f, lr1 = 0.f;
    const int row0 = qt * 64 + w * 16 + (l >> 2);   // global q row (and +8)

    for (int jt = 0; jt <= qt; jt++) {
        // K(jt) ready (V(jt) may still be in flight — it's the newest group)
        CP_WAIT(1);
        __syncthreads();

        // ---- S = Q K^T (3-pass split) ----
#pragma unroll
        for (int nt = 0; nt < 8; nt++) {
            S[nt][0] = S[nt][1] = S[nt][2] = S[nt][3] = 0.f;
        }
#pragma unroll
        for (int ks = 0; ks < 8; ks++) {
            uint32_t ah[4], al2[4], bh[4][4], bl[4][4];
            uint32_t aoff = (uint32_t)((w * 16 + (l & 15)) * LDF
                                       + ks * 16 + 8 * (l >> 4)) * 2;
            ldsm_x4(ah,  sQH + aoff);
            ldsm_x4(al2, sQL + aoff);
#pragma unroll
            for (int p = 0; p < 4; p++) {
                uint32_t boff = (uint32_t)((p * 16 + 8 * (l >> 4) + (l & 7)) * LDF
                                           + ks * 16 + 8 * ((l >> 3) & 1)) * 2;
                ldsm_x4(bh[p], sKH + boff);
                ldsm_x4(bl[p], sKL + boff);
            }
#pragma unroll
            for (int nt = 0; nt < 8; nt++) {
                const uint32_t* Bh_ = &bh[nt >> 1][(nt & 1) * 2];
                const uint32_t* Bl_ = &bl[nt >> 1][(nt & 1) * 2];
                mma16816(S[nt], ah,  Bh_);
                mma16816(S[nt], ah,  Bl_);
                mma16816(S[nt], al2, Bh_);
            }
        }
        __syncthreads();                    // K consumed by all warps
        if (jt < qt) LOAD_K(jt + 1);        // prefetch next K into same bufs

        // ---- scale + causal mask ----
        const bool diag = (jt == qt);
#pragma unroll
        for (int nt = 0; nt < 8; nt++)
#pragma unroll
            for (int j = 0; j < 4; j++) {
                float v = S[nt][j] * ATT_SCALE;
                if (diag) {
                    int c = jt * 64 + nt * 8 + 2 * (l & 3) + (j & 1);
                    int r = row0 + (j >> 1) * 8;
                    if (c > r) v = -1e30f;
                }
                S[nt][j] = v;
            }

        // ---- online softmax (registers only) ----
        float mx0 = -1e30f, mx1 = -1e30f;
#pragma unroll
        for (int nt = 0; nt < 8; nt++) {
            mx0 = fmaxf(mx0, fmaxf(S[nt][0], S[nt][1]));
            mx1 = fmaxf(mx1, fmaxf(S[nt][2], S[nt][3]));
        }
        mx0 = fmaxf(mx0, __shfl_xor_sync(0xffffffffu, mx0, 1));
        mx0 = fmaxf(mx0, __shfl_xor_sync(0xffffffffu, mx0, 2));
        mx1 = fmaxf(mx1, __shfl_xor_sync(0xffffffffu, mx1, 1));
        mx1 = fmaxf(mx1, __shfl_xor_sync(0xffffffffu, mx1, 2));
        float mn0 = fmaxf(m0, mx0), mn1 = fmaxf(m1, mx1);
        float a0 = __expf(m0 - mn0), a1 = __expf(m1 - mn1);
        float s0 = 0.f, s1 = 0.f;
#pragma unroll
        for (int nt = 0; nt < 8; nt++) {
            S[nt][0] = __expf(S[nt][0] - mn0);
            S[nt][1] = __expf(S[nt][1] - mn0);
            S[nt][2] = __expf(S[nt][2] - mn1);
            S[nt][3] = __expf(S[nt][3] - mn1);
            s0 += S[nt][0] + S[nt][1];
            s1 += S[nt][2] + S[nt][3];
        }
        s0 += __shfl_xor_sync(0xffffffffu, s0, 1);
        s0 += __shfl_xor_sync(0xffffffffu, s0, 2);
        s1 += __shfl_xor_sync(0xffffffffu, s1, 1);
        s1 += __shfl_xor_sync(0xffffffffu, s1, 2);
        lr0 = lr0 * a0 + s0;
        lr1 = lr1 * a1 + s1;
        m0 = mn0; m1 = mn1;
#pragma unroll
        for (int nt = 0; nt < 16; nt++) {
            O[nt][0] *= a0; O[nt][1] *= a0;
            O[nt][2] *= a1; O[nt][3] *= a1;
        }

        // V(jt) ready: it is older than K(jt+1) (in-order retirement)
        if (jt < qt) { CP_WAIT(1); } else { CP_WAIT(0); }
        __syncthreads();

        // ---- O += P V (3-pass: PhVh + PhVl + PlVh); V^T via ldmatrix.trans ----
#pragma unroll
        for (int kk = 0; kk < 4; kk++) {
            uint32_t ph[4], pl[4];
            {
                float p00 = S[2 * kk][0],     p01 = S[2 * kk][1];
                float p10 = S[2 * kk][2],     p11 = S[2 * kk][3];
                float p20 = S[2 * kk + 1][0], p21 = S[2 * kk + 1][1];
                float p30 = S[2 * kk + 1][2], p31 = S[2 * kk + 1][3];
                float h00 = __bfloat162float(__float2bfloat16(p00));
                float h01 = __bfloat162float(__float2bfloat16(p01));
                float h10 = __bfloat162float(__float2bfloat16(p10));
                float h11 = __bfloat162float(__float2bfloat16(p11));
                float h20 = __bfloat162float(__float2bfloat16(p20));
                float h21 = __bfloat162float(__float2bfloat16(p21));
                float h30 = __bfloat162float(__float2bfloat16(p30));
                float h31 = __bfloat162float(__float2bfloat16(p31));
                ph[0] = pack_bf(h00, h01); ph[1] = pack_bf(h10, h11);
                ph[2] = pack_bf(h20, h21); ph[3] = pack_bf(h30, h31);
                pl[0] = pack_bf(p00 - h00, p01 - h01);
                pl[1] = pack_bf(p10 - h10, p11 - h11);
                pl[2] = pack_bf(p20 - h20, p21 - h21);
                pl[3] = pack_bf(p30 - h30, p31 - h31);
            }
#pragma unroll
            for (int g = 0; g < 8; g++) {
                uint32_t vh[4], vl[4];
                uint32_t voff = (uint32_t)((kk * 16 + (l & 15)) * LDF
                                           + g * 16 + 8 * (l >> 4)) * 2;
                ldsm_x4_t(vh, sVH + voff);
                ldsm_x4_t(vl, sVL + voff);
                mma16816(O[2 * g],     ph, &vh[0]);
                mma16816(O[2 * g],     ph, &vl[0]);
                mma16816(O[2 * g],     pl, &vh[0]);
                mma16816(O[2 * g + 1], ph, &vh[2]);
                mma16816(O[2 * g + 1], ph, &vl[2]);
                mma16816(O[2 * g + 1], pl, &vh[2]);
            }
        }
        __syncthreads();                    // V consumed by all warps
        if (jt < qt) LOAD_V(jt + 1);        // prefetch next V into same bufs
    }

    // ---- normalize + write split-bf16 AO directly ----
    float inv0 = 1.f / lr0, inv1 = 1.f / lr1;
    const size_t obase = (size_t)row0 * QD + h * HD;
#pragma unroll
    for (int nt = 0; nt < 16; nt++) {
        int col = nt * 8 + 2 * (l & 3);
        float f0 = O[nt][0] * inv0, f1 = O[nt][1] * inv0;
        float f2 = O[nt][2] * inv1, f3 = O[nt][3] * inv1;
        __nv_bfloat16 h0 = __float2bfloat16(f0), h1 = __float2bfloat16(f1);
        __nv_bfloat16 h2 = __float2bfloat16(f2), h3 = __float2bfloat16(f3);
        __nv_bfloat162 hv01{h0, h1}, hv23{h2, h3};
        __nv_bfloat162 lv01{__float2bfloat16(f0 - __bfloat162float(h0)),
                            __float2bfloat16(f1 - __bfloat162float(h1))};
        __nv_bfloat162 lv23{__float2bfloat16(f2 - __bfloat162float(h2)),
                            __float2bfloat16(f3 - __bfloat162float(h3))};
        *(__nv_bfloat162*)(g_AOH + obase + col)          = hv01;
        *(__nv_bfloat162*)(g_AOL + obase + col)          = lv01;
        *(__nv_bfloat162*)(g_AOH + obase + 8 * QD + col) = hv23;
        *(__nv_bfloat162*)(g_AOL + obase + 8 * QD + col) = lv23;
    }
#undef LOAD_K
#undef LOAD_V
}

// ---------------------------------------------------------------------------
// Launch
// ---------------------------------------------------------------------------
extern "C" void kernel_launch(void* const* d_in, const int* in_sizes, int n_in,
                              void* d_out, int out_size)
{
    const float* hs   = (const float*)d_in[0];
    const float* cosb = (const float*)d_in[1];
    const float* sinb = (const float*)d_in[2];
    const float* wq   = (const float*)d_in[3];
    const float* wk   = (const float*)d_in[4];
    const float* wv   = (const float*)d_in[5];
    const float* wo   = (const float*)d_in[6];
    // d_in[7..9] (k_cache, v_cache, block_ids): scatter/gather is an identity.
    float* out = (float*)d_out;

    cudaFuncSetAttribute(qkv_mma_kernel,
                         cudaFuncAttributeMaxDynamicSharedMemorySize, GEMM_SMEM);
    cudaFuncSetAttribute(o_mma_kernel,
                         cudaFuncAttributeMaxDynamicSharedMemorySize, GEMM_SMEM);
    cudaFuncSetAttribute(flash_mma_kernel,
                         cudaFuncAttributeMaxDynamicSharedMemorySize, FLASH_SMEM);

    // 1) fp32 -> split-bf16 conversions (dst chosen device-side via tag)
    {
        const int nh = S_LEN * HID;
        cvt_sel_kernel<<<nh / 1024, 256>>>(hs, 0, 0, nh);
        const int nq = QD * HID;
        cvt_sel_kernel<<<nq / 1024, 256>>>(wq, 1, 0, nq);
        const int nk = KVD * HID;
        cvt_sel_kernel<<<nk / 1024, 256>>>(wk, 1, (size_t)QD * HID, nk);
        cvt_sel_kernel<<<nk / 1024, 256>>>(wv, 1, (size_t)(QD + KVD) * HID, nk);
        const int no = HID * QD;
        cvt_sel_kernel<<<no / 1024, 256>>>(wo, 2, 0, no);
    }

    // 2) QKV projections on HMMA
    qkv_mma_kernel<<<dim3(48, 16), 256, GEMM_SMEM>>>();

    // 3) RoPE on Q and K (fp32)
    {
        int total = S_LEN * NH * 64 + S_LEN * NKV * 64;
        rope_kernel<<<(total + 255) / 256, 256>>>(cosb, sinb);
    }

    // 4) Q/K/V -> split bf16
    {
        int total = S_LEN * QD + 2 * S_LEN * KVD;
        cvt_qkv_kernel<<<total / 1024, 256>>>();
    }

    // 5) HMMA causal flash attention (writes split-bf16 AO directly)
    flash_mma_kernel<<<dim3(32, 32), 128, FLASH_SMEM>>>();

    // 6) O projection on HMMA
    o_mma_kernel<<<dim3(32, 16), 256, GEMM_SMEM>>>(out);
}

// round 8
// speedup vs baseline: 1.0016x; 1.0016x over previous
#include <cuda_runtime.h>
#include <cuda_bf16.h>
#include <cstdint>

#define S_LEN 2048
#define HID   4096
#define NH    32
#define NKV   8
#define HD    128
#define KVD   (NKV*HD)   /* 1024 */
#define QD    (NH*HD)    /* 4096 */
#define WROWS (QD+2*KVD) /* 6144 */
#define ATT_SCALE 0.08838834764831845f

// ---------------------------------------------------------------------------
// Scratch (device globals; no runtime allocation allowed)
// ---------------------------------------------------------------------------
__device__ float g_Q [S_LEN*QD];   // Q projection (fp32, pre-RoPE)
__device__ float g_K [S_LEN*KVD];  // K projection (fp32, pre-RoPE)
__device__ float g_V [S_LEN*KVD];

// bf16 split operands (x = hi + lo)
__device__ __nv_bfloat16 g_hsH[S_LEN*HID], g_hsL[S_LEN*HID];
__device__ __nv_bfloat16 g_WH [WROWS*HID], g_WL [WROWS*HID];   // wq|wk|wv stacked
__device__ __nv_bfloat16 g_WOH[HID*QD],    g_WOL[HID*QD];
__device__ __nv_bfloat16 g_AOH[S_LEN*QD],  g_AOL[S_LEN*QD];
// split Q/K/V for HMMA flash (post-RoPE)
__device__ __nv_bfloat16 g_QH[S_LEN*QD],  g_QL[S_LEN*QD];
__device__ __nv_bfloat16 g_KH[S_LEN*KVD], g_KL[S_LEN*KVD];
__device__ __nv_bfloat16 g_VH[S_LEN*KVD], g_VL[S_LEN*KVD];

// ---------------------------------------------------------------------------
// mma.sync helpers (sm_80-level, compiles for compute_103)
// ---------------------------------------------------------------------------
__device__ __forceinline__ uint32_t smem_u32(const void* p) {
    uint32_t a;
    asm("{ .reg .u64 t; cvta.to.shared.u64 t, %1; cvt.u32.u64 %0, t; }"
        : "=r"(a) : "l"(p));
    return a;
}

__device__ __forceinline__ void ldsm_x4(uint32_t* r, uint32_t addr) {
    asm volatile("ldmatrix.sync.aligned.m8n8.x4.shared.b16 {%0,%1,%2,%3}, [%4];"
        : "=r"(r[0]), "=r"(r[1]), "=r"(r[2]), "=r"(r[3]) : "r"(addr));
}

__device__ __forceinline__ void ldsm_x4_t(uint32_t* r, uint32_t addr) {
    asm volatile("ldmatrix.sync.aligned.m8n8.x4.trans.shared.b16 {%0,%1,%2,%3}, [%4];"
        : "=r"(r[0]), "=r"(r[1]), "=r"(r[2]), "=r"(r[3]) : "r"(addr));
}

__device__ __forceinline__ void mma16816(float* d, const uint32_t* a,
                                         const uint32_t* b) {
    asm volatile(
        "mma.sync.aligned.m16n8k16.row.col.f32.bf16.bf16.f32 "
        "{%0,%1,%2,%3},{%4,%5,%6,%7},{%8,%9},{%0,%1,%2,%3};"
        : "+f"(d[0]), "+f"(d[1]), "+f"(d[2]), "+f"(d[3])
        : "r"(a[0]), "r"(a[1]), "r"(a[2]), "r"(a[3]), "r"(b[0]), "r"(b[1]));
}

__device__ __forceinline__ void cp16(uint32_t saddr, const void* g) {
    asm volatile("cp.async.cg.shared.global [%0], [%1], 16;"
        :: "r"(saddr), "l"(g) : "memory");
}

#define CP_COMMIT() asm volatile("cp.async.commit_group;" ::: "memory")
#define CP_WAIT(n)  asm volatile("cp.async.wait_group %0;" :: "n"(n) : "memory")

// pack two f32 -> bf16x2 (lo first)
__device__ __forceinline__ uint32_t pack_bf(float lo, float hi) {
    uint32_t r;
    asm("cvt.rn.bf16x2.f32 %0, %1, %2;" : "=r"(r) : "f"(hi), "f"(lo));
    return r;
}

// ---------------------------------------------------------------------------
// Split-bf16 HMMA GEMM: C[128,128] = (Ah+Al)[128,K] @ (Bh+Bl)[128,K]^T
// 256 threads, warp grid 2(m) x 4(n), warp tile 64x32. BK=32, double buffered.
// NO register cap: let ptxas pick (R7's cap of 128 likely caused spills).
// ---------------------------------------------------------------------------
#define LDT      40
#define TILE_B   (128*LDT*2)
#define STAGE_B  (4*TILE_B)
#define GEMM_SMEM (2*STAGE_B)

__device__ __forceinline__ void mma_gemm(
    const __nv_bfloat16* __restrict__ pAh, const __nv_bfloat16* __restrict__ pAl,
    const __nv_bfloat16* __restrict__ pBh, const __nv_bfloat16* __restrict__ pBl,
    int K, float* __restrict__ Cp, int ldc)
{
    extern __shared__ char smc[];
    const uint32_t smb = smem_u32(smc);
    const int tid = threadIdx.x;
    const int wid = tid >> 5;
    const int l   = tid & 31;
    const int wm  = wid & 1;
    const int wn  = wid >> 1;

    float acc[4][4][4] = {};
    const int nk = K >> 5;

#define ISSUE_STAGE(s, kb) do {                                              \
        uint32_t sb_ = smb + (s) * STAGE_B;                                  \
        _Pragma("unroll")                                                    \
        for (int t = 0; t < 8; t++) {                                        \
            const int tile = t >> 1;                                         \
            int idx2 = tid + (t & 1) * 256;                                  \
            int row  = idx2 >> 2;                                            \
            int ch   = idx2 & 3;                                             \
            const __nv_bfloat16* src =                                       \
                (tile == 0) ? pAh : (tile == 1) ? pAl :                      \
                (tile == 2) ? pBh : pBl;                                     \
            cp16(sb_ + tile * TILE_B + (row * LDT + ch * 8) * 2,             \
                 src + (size_t)row * K + (kb) + ch * 8);                     \
        }                                                                    \
        CP_COMMIT();                                                         \
    } while (0)

    ISSUE_STAGE(0, 0);

    for (int kt = 0; kt < nk; kt++) {
        const int s = kt & 1;
        if (kt + 1 < nk) {
            ISSUE_STAGE(s ^ 1, (kt + 1) << 5);
            CP_WAIT(1);
        } else {
            CP_WAIT(0);
        }
        __syncthreads();

        const uint32_t sb  = smb + s * STAGE_B;
        const uint32_t aAh = sb;
        const uint32_t aAl = sb + TILE_B;
        const uint32_t aBh = sb + 2 * TILE_B;
        const uint32_t aBl = sb + 3 * TILE_B;

#pragma unroll
        for (int ks = 0; ks < 2; ks++) {
            const int k0 = ks * 16;
            uint32_t ah[4][4], al[4][4], bh[2][4], bl[2][4];
#pragma unroll
            for (int mt = 0; mt < 4; mt++) {
                uint32_t off = (uint32_t)((wm * 64 + mt * 16 + (l & 15)) * LDT
                                          + k0 + 8 * (l >> 4)) * 2;
                ldsm_x4(ah[mt], aAh + off);
                ldsm_x4(al[mt], aAl + off);
            }
#pragma unroll
            for (int p = 0; p < 2; p++) {
                uint32_t off = (uint32_t)((wn * 32 + p * 16 + 8 * (l >> 4) + (l & 7)) * LDT
                                          + k0 + 8 * ((l >> 3) & 1)) * 2;
                ldsm_x4(bh[p], aBh + off);
                ldsm_x4(bl[p], aBl + off);
            }
#pragma unroll
            for (int mt = 0; mt < 4; mt++)
#pragma unroll
                for (int nt = 0; nt < 4; nt++) {
                    const uint32_t* Bh_ = &bh[nt >> 1][(nt & 1) * 2];
                    const uint32_t* Bl_ = &bl[nt >> 1][(nt & 1) * 2];
                    mma16816(acc[mt][nt], ah[mt], Bh_);
                    mma16816(acc[mt][nt], ah[mt], Bl_);
                    mma16816(acc[mt][nt], al[mt], Bh_);
                }
        }
        __syncthreads();
    }

    const int m_base = wm * 64;
    const int n_base = wn * 32;
#pragma unroll
    for (int mt = 0; mt < 4; mt++)
#pragma unroll
        for (int nt = 0; nt < 4; nt++) {
            int row = m_base + mt * 16 + (l >> 2);
            int col = n_base + nt * 8 + 2 * (l & 3);
            float2 v0 = {acc[mt][nt][0], acc[mt][nt][1]};
            float2 v1 = {acc[mt][nt][2], acc[mt][nt][3]};
            *(float2*)(Cp + (size_t)row * ldc + col)       = v0;
            *(float2*)(Cp + (size_t)(row + 8) * ldc + col) = v1;
        }
#undef ISSUE_STAGE
}

__global__ void __launch_bounds__(256) qkv_mma_kernel()
{
    const int bx = blockIdx.x;
    const int m0 = blockIdx.y * 128;
    float* C; int ldc, n0;
    if (bx < 32)      { C = g_Q; ldc = QD;  n0 = bx << 7; }
    else if (bx < 40) { C = g_K; ldc = KVD; n0 = (bx - 32) << 7; }
    else              { C = g_V; ldc = KVD; n0 = (bx - 40) << 7; }
    mma_gemm(g_hsH + (size_t)m0 * HID, g_hsL + (size_t)m0 * HID,
             g_WH  + (size_t)(bx << 7) * HID, g_WL + (size_t)(bx << 7) * HID,
             HID, C + (size_t)m0 * ldc + n0, ldc);
}

__global__ void __launch_bounds__(256) o_mma_kernel(float* __restrict__ out)
{
    const int m0 = blockIdx.y * 128;
    const int n0 = blockIdx.x * 128;
    mma_gemm(g_AOH + (size_t)m0 * QD, g_AOL + (size_t)m0 * QD,
             g_WOH + (size_t)n0 * QD, g_WOL + (size_t)n0 * QD,
             QD, out + (size_t)m0 * HID + n0, HID);
}

// ---------------------------------------------------------------------------
// fp32 -> bf16 hi/lo split helper
// ---------------------------------------------------------------------------
__device__ __forceinline__ void cvt4(const float* __restrict__ src,
                                     __nv_bfloat16* __restrict__ hi,
                                     __nv_bfloat16* __restrict__ lo, int i)
{
    float4 x = *(const float4*)(src + i);
    __nv_bfloat16 h0 = __float2bfloat16(x.x);
    __nv_bfloat16 h1 = __float2bfloat16(x.y);
    __nv_bfloat16 h2 = __float2bfloat16(x.z);
    __nv_bfloat16 h3 = __float2bfloat16(x.w);
    __nv_bfloat16 l0 = __float2bfloat16(x.x - __bfloat162float(h0));
    __nv_bfloat16 l1 = __float2bfloat16(x.y - __bfloat162float(h1));
    __nv_bfloat16 l2 = __float2bfloat16(x.z - __bfloat162float(h2));
    __nv_bfloat16 l3 = __float2bfloat16(x.w - __bfloat162float(h3));
    __nv_bfloat162 hv0{h0, h1}, hv1{h2, h3}, lv0{l0, l1}, lv1{l2, l3};
    *(__nv_bfloat162*)(hi + i)     = hv0;
    *(__nv_bfloat162*)(hi + i + 2) = hv1;
    *(__nv_bfloat162*)(lo + i)     = lv0;
    *(__nv_bfloat162*)(lo + i + 2) = lv1;
}

// Single merged conversion kernel for hs + all weights (dst device-side —
// never pass __device__ symbols from host; ATS silently writes host RAM).
__global__ void cvt_all_kernel(const float* __restrict__ hs,
                               const float* __restrict__ wq,
                               const float* __restrict__ wk,
                               const float* __restrict__ wv,
                               const float* __restrict__ wo)
{
    const int NH4  = S_LEN * HID / 4;    // 2097152
    const int NWQ4 = QD * HID / 4;       // 4194304
    const int NWK4 = KVD * HID / 4;      // 1048576
    int i4 = blockIdx.x * blockDim.x + threadIdx.x;
    if (i4 < NH4) {
        cvt4(hs, g_hsH, g_hsL, i4 << 2);
        return;
    }
    i4 -= NH4;
    if (i4 < NWQ4) { cvt4(wq, g_WH, g_WL, i4 << 2); return; }
    i4 -= NWQ4;
    if (i4 < NWK4) {
        cvt4(wk, g_WH + (size_t)QD * HID, g_WL + (size_t)QD * HID, i4 << 2);
        return;
    }
    i4 -= NWK4;
    if (i4 < NWK4) {
        cvt4(wv, g_WH + (size_t)(QD + KVD) * HID,
                 g_WL + (size_t)(QD + KVD) * HID, i4 << 2);
        return;
    }
    i4 -= NWK4;
    if (i4 < NWQ4) cvt4(wo, g_WOH, g_WOL, i4 << 2);
}
#define CVT_ALL_BLOCKS ((S_LEN*HID/4 + QD*HID/4 + 2*(KVD*HID/4) + QD*HID/4) / 256)

// ---------------------------------------------------------------------------
// Fused RoPE + split: reads fp32 Q/K, writes rotated split-bf16 QH/QL/KH/KL;
// also splits V (pass-through) in the same launch. Replaces rope + cvt_qkv.
// ---------------------------------------------------------------------------
__global__ void rope_split_kernel(const float* __restrict__ cosb,
                                  const float* __restrict__ sinb)
{
    int idx = blockIdx.x * blockDim.x + threadIdx.x;
    const int qtot = S_LEN * NH * 64;           // 4194304
    const int ktot = S_LEN * NKV * 64;          // 1048576
    const int vtot = S_LEN * KVD / 4;           // 524288
    if (idx < qtot) {
        int d = idx & 63;
        int h = (idx >> 6) & 31;
        int s = idx >> 11;
        float c  = cosb[s * HD + d];
        float sn = sinb[s * HD + d];
        const float* base = g_Q + (size_t)s * QD + h * HD;
        float x1 = base[d], x2 = base[d + 64];
        float r1 = x1 * c - x2 * sn;
        float r2 = x2 * c + x1 * sn;
        size_t o = (size_t)s * QD + h * HD + d;
        __nv_bfloat16 h1 = __float2bfloat16(r1);
        __nv_bfloat16 h2 = __float2bfloat16(r2);
        g_QH[o]      = h1;
        g_QH[o + 64] = h2;
        g_QL[o]      = __float2bfloat16(r1 - __bfloat162float(h1));
        g_QL[o + 64] = __float2bfloat16(r2 - __bfloat162float(h2));
    } else if (idx < qtot + ktot) {
        int j = idx - qtot;
        int d = j & 63;
        int h = (j >> 6) & 7;
        int s = j >> 9;
        float c  = cosb[s * HD + d];
        float sn = sinb[s * HD + d];
        const float* base = g_K + (size_t)s * KVD + h * HD;
        float x1 = base[d], x2 = base[d + 64];
        float r1 = x1 * c - x2 * sn;
        float r2 = x2 * c + x1 * sn;
        size_t o = (size_t)s * KVD + h * HD + d;
        __nv_bfloat16 h1 = __float2bfloat16(r1);
        __nv_bfloat16 h2 = __float2bfloat16(r2);
        g_KH[o]      = h1;
        g_KH[o + 64] = h2;
        g_KL[o]      = __float2bfloat16(r1 - __bfloat162float(h1));
        g_KL[o + 64] = __float2bfloat16(r2 - __bfloat162float(h2));
    } else if (idx < qtot + ktot + vtot) {
        int j = idx - qtot - ktot;
        cvt4(g_V, g_VH, g_VL, j << 2);
    }
}
#define ROPE_TOTAL (S_LEN*NH*64 + S_LEN*NKV*64 + S_LEN*KVD/4)

// ---------------------------------------------------------------------------
// HMMA causal flash attention (split-bf16, 3-pass for QK and PV).
// Pipelined: K(j+1) issued after QK(j); V(j+1) issued after PV(j).
// Writes split-bf16 AO directly.
// ---------------------------------------------------------------------------
#define LDF 136
#define FTILE (64*LDF*2)            /* 17408 B */
#define FLASH_SMEM (6*FTILE)        /* 104448 B -> 2 CTAs/SM */

__global__ void __launch_bounds__(128) flash_mma_kernel()
{
    extern __shared__ char fsm[];
    const uint32_t smb = smem_u32(fsm);
    const int tid = threadIdx.x;
    const int w   = tid >> 5;
    const int l   = tid & 31;
    const int qt  = 31 - (int)blockIdx.x;
    const int h   = blockIdx.y;
    const int kvh = h >> 2;

    const uint32_t sQH = smb;
    const uint32_t sQL = smb + FTILE;
    const uint32_t sKH = smb + 2 * FTILE;
    const uint32_t sKL = smb + 3 * FTILE;
    const uint32_t sVH = smb + 4 * FTILE;
    const uint32_t sVL = smb + 5 * FTILE;

#define LOAD_K(jt_) do {                                                     \
        const size_t kb_ = (size_t)((jt_) * 64) * KVD + kvh * HD;            \
        _Pragma("unroll")                                                    \
        for (int t = 0; t < 8; t++) {                                        \
            int idx = tid + t * 128;                                         \
            int row = idx >> 4, c8 = (idx & 15) << 3;                        \
            uint32_t doff = (uint32_t)(row * LDF + c8) * 2;                  \
            size_t gs = kb_ + (size_t)row * KVD + c8;                        \
            cp16(sKH + doff, g_KH + gs);                                     \
            cp16(sKL + doff, g_KL + gs);                                     \
        }                                                                    \
        CP_COMMIT();                                                         \
    } while (0)

#define LOAD_V(jt_) do {                                                     \
        const size_t kb_ = (size_t)((jt_) * 64) * KVD + kvh * HD;            \
        _Pragma("unroll")                                                    \
        for (int t = 0; t < 8; t++) {                                        \
            int idx = tid + t * 128;                                         \
            int row = idx >> 4, c8 = (idx & 15) << 3;                        \
            uint32_t doff = (uint32_t)(row * LDF + c8) * 2;                  \
            size_t gs = kb_ + (size_t)row * KVD + c8;                        \
            cp16(sVH + doff, g_VH + gs);                                     \
            cp16(sVL + doff, g_VL + gs);                                     \
        }                                                                    \
        CP_COMMIT();                                                         \
    } while (0)

    // Load Q tile (group 0), then K(0) (group 1), V(0) (group 2).
    {
        const size_t qbase = (size_t)(qt * 64) * QD + h * HD;
#pragma unroll
        for (int t = 0; t < 8; t++) {
            int idx = tid + t * 128;
            int row = idx >> 4, c8 = (idx & 15) << 3;
            uint32_t doff = (uint32_t)(row * LDF + c8) * 2;
            cp16(sQH + doff, g_QH + qbase + (size_t)row * QD + c8);
            cp16(sQL + doff, g_QL + qbase + (size_t)row * QD + c8);
        }
        CP_COMMIT();
    }
    LOAD_K(0);
    LOAD_V(0);

    float S[8][4];
    float O[16][4] = {};
    float m0 = -1e30f, m1 = -1e30f, lr0 = 0.f, lr1 = 0.f;
    const int row0 = qt * 64 + w * 16 + (l >> 2);   // global q row (and +8)

    for (int jt = 0; jt <= qt; jt++) {
        // K(jt) ready (V(jt) may still be in flight — newest group)
        CP_WAIT(1);
        __syncthreads();

        // ---- S = Q K^T (3-pass split) ----
#pragma unroll
        for (int nt = 0; nt < 8; nt++) {
            S[nt][0] = S[nt][1] = S[nt][2] = S[nt][3] = 0.f;
        }
#pragma unroll
        for (int ks = 0; ks < 8; ks++) {
            uint32_t ah[4], al2[4], bh[4][4], bl[4][4];
            uint32_t aoff = (uint32_t)((w * 16 + (l & 15)) * LDF
                                       + ks * 16 + 8 * (l >> 4)) * 2;
            ldsm_x4(ah,  sQH + aoff);
            ldsm_x4(al2, sQL + aoff);
#pragma unroll
            for (int p = 0; p < 4; p++) {
                uint32_t boff = (uint32_t)((p * 16 + 8 * (l >> 4) + (l & 7)) * LDF
                                           + ks * 16 + 8 * ((l >> 3) & 1)) * 2;
                ldsm_x4(bh[p], sKH + boff);
                ldsm_x4(bl[p], sKL + boff);
            }
#pragma unroll
            for (int nt = 0; nt < 8; nt++) {
                const uint32_t* Bh_ = &bh[nt >> 1][(nt & 1) * 2];
                const uint32_t* Bl_ = &bl[nt >> 1][(nt & 1) * 2];
                mma16816(S[nt], ah,  Bh_);
                mma16816(S[nt], ah,  Bl_);
                mma16816(S[nt], al2, Bh_);
            }
        }
        __syncthreads();                    // K consumed by all warps
        if (jt < qt) LOAD_K(jt + 1);        // prefetch next K

        // ---- scale + causal mask ----
        const bool diag = (jt == qt);
#pragma unroll
        for (int nt = 0; nt < 8; nt++)
#pragma unroll
            for (int j = 0; j < 4; j++) {
                float v = S[nt][j] * ATT_SCALE;
                if (diag) {
                    int c = jt * 64 + nt * 8 + 2 * (l & 3) + (j & 1);
                    int r = row0 + (j >> 1) * 8;
                    if (c > r) v = -1e30f;
                }
                S[nt][j] = v;
            }

        // ---- online softmax (registers only) ----
        float mx0 = -1e30f, mx1 = -1e30f;
#pragma unroll
        for (int nt = 0; nt < 8; nt++) {
            mx0 = fmaxf(mx0, fmaxf(S[nt][0], S[nt][1]));
            mx1 = fmaxf(mx1, fmaxf(S[nt][2], S[nt][3]));
        }
        mx0 = fmaxf(mx0, __shfl_xor_sync(0xffffffffu, mx0, 1));
        mx0 = fmaxf(mx0, __shfl_xor_sync(0xffffffffu, mx0, 2));
        mx1 = fmaxf(mx1, __shfl_xor_sync(0xffffffffu, mx1, 1));
        mx1 = fmaxf(mx1, __shfl_xor_sync(0xffffffffu, mx1, 2));
        float mn0 = fmaxf(m0, mx0), mn1 = fmaxf(m1, mx1);
        float a0 = __expf(m0 - mn0), a1 = __expf(m1 - mn1);
        float s0 = 0.f, s1 = 0.f;
#pragma unroll
        for (int nt = 0; nt < 8; nt++) {
            S[nt][0] = __expf(S[nt][0] - mn0);
            S[nt][1] = __expf(S[nt][1] - mn0);
            S[nt][2] = __expf(S[nt][2] - mn1);
            S[nt][3] = __expf(S[nt][3] - mn1);
            s0 += S[nt][0] + S[nt][1];
            s1 += S[nt][2] + S[nt][3];
        }
        s0 += __shfl_xor_sync(0xffffffffu, s0, 1);
        s0 += __shfl_xor_sync(0xffffffffu, s0, 2);
        s1 += __shfl_xor_sync(0xffffffffu, s1, 1);
        s1 += __shfl_xor_sync(0xffffffffu, s1, 2);
        lr0 = lr0 * a0 + s0;
        lr1 = lr1 * a1 + s1;
        m0 = mn0; m1 = mn1;
#pragma unroll
        for (int nt = 0; nt < 16; nt++) {
            O[nt][0] *= a0; O[nt][1] *= a0;
            O[nt][2] *= a1; O[nt][3] *= a1;
        }

        // V(jt) ready: older than K(jt+1) (in-order retirement)
        if (jt < qt) { CP_WAIT(1); } else { CP_WAIT(0); }
        __syncthreads();

        // ---- O += P V (3-pass); V^T via ldmatrix.trans ----
#pragma unroll
        for (int kk = 0; kk < 4; kk++) {
            uint32_t ph[4], pl[4];
            {
                float p00 = S[2 * kk][0],     p01 = S[2 * kk][1];
                float p10 = S[2 * kk][2],     p11 = S[2 * kk][3];
                float p20 = S[2 * kk + 1][0], p21 = S[2 * kk + 1][1];
                float p30 = S[2 * kk + 1][2], p31 = S[2 * kk + 1][3];
                float h00 = __bfloat162float(__float2bfloat16(p00));
                float h01 = __bfloat162float(__float2bfloat16(p01));
                float h10 = __bfloat162float(__float2bfloat16(p10));
                float h11 = __bfloat162float(__float2bfloat16(p11));
                float h20 = __bfloat162float(__float2bfloat16(p20));
                float h21 = __bfloat162float(__float2bfloat16(p21));
                float h30 = __bfloat162float(__float2bfloat16(p30));
                float h31 = __bfloat162float(__float2bfloat16(p31));
                ph[0] = pack_bf(h00, h01); ph[1] = pack_bf(h10, h11);
                ph[2] = pack_bf(h20, h21); ph[3] = pack_bf(h30, h31);
                pl[0] = pack_bf(p00 - h00, p01 - h01);
                pl[1] = pack_bf(p10 - h10, p11 - h11);
                pl[2] = pack_bf(p20 - h20, p21 - h21);
                pl[3] = pack_bf(p30 - h30, p31 - h31);
            }
#pragma unroll
            for (int g = 0; g < 8; g++) {
                uint32_t vh[4], vl[4];
                uint32_t voff = (uint32_t)((kk * 16 + (l & 15)) * LDF
                                           + g * 16 + 8 * (l >> 4)) * 2;
                ldsm_x4_t(vh, sVH + voff);
                ldsm_x4_t(vl, sVL + voff);
                mma16816(O[2 * g],     ph, &vh[0]);
                mma16816(O[2 * g],     ph, &vl[0]);
                mma16816(O[2 * g],     pl, &vh[0]);
                mma16816(O[2 * g + 1], ph, &vh[2]);
                mma16816(O[2 * g + 1], ph, &vl[2]);
                mma16816(O[2 * g + 1], pl, &vh[2]);
            }
        }
        __syncthreads();                    // V consumed by all warps
        if (jt < qt) LOAD_V(jt + 1);        // prefetch next V
    }

    // ---- normalize + write split-bf16 AO directly ----
    float inv0 = 1.f / lr0, inv1 = 1.f / lr1;
    const size_t obase = (size_t)row0 * QD + h * HD;
#pragma unroll
    for (int nt = 0; nt < 16; nt++) {
        int col = nt * 8 + 2 * (l & 3);
        float f0 = O[nt][0] * inv0, f1 = O[nt][1] * inv0;
        float f2 = O[nt][2] * inv1, f3 = O[nt][3] * inv1;
        __nv_bfloat16 h0 = __float2bfloat16(f0), h1 = __float2bfloat16(f1);
        __nv_bfloat16 h2 = __float2bfloat16(f2), h3 = __float2bfloat16(f3);
        __nv_bfloat162 hv01{h0, h1}, hv23{h2, h3};
        __nv_bfloat162 lv01{__float2bfloat16(f0 - __bfloat162float(h0)),
                            __float2bfloat16(f1 - __bfloat162float(h1))};
        __nv_bfloat162 lv23{__float2bfloat16(f2 - __bfloat162float(h2)),
                            __float2bfloat16(f3 - __bfloat162float(h3))};
        *(__nv_bfloat162*)(g_AOH + obase + col)          = hv01;
        *(__nv_bfloat162*)(g_AOL + obase + col)          = lv01;
        *(__nv_bfloat162*)(g_AOH + obase + 8 * QD + col) = hv23;
        *(__nv_bfloat162*)(g_AOL + obase + 8 * QD + col) = lv23;
    }
#undef LOAD_K
#undef LOAD_V
}

// ---------------------------------------------------------------------------
// Launch
// ---------------------------------------------------------------------------
extern "C" void kernel_launch(void* const* d_in, const int* in_sizes, int n_in,
                              void* d_out, int out_size)
{
    const float* hs   = (const float*)d_in[0];
    const float* cosb = (const float*)d_in[1];
    const float* sinb = (const float*)d_in[2];
    const float* wq   = (const float*)d_in[3];
    const float* wk   = (const float*)d_in[4];
    const float* wv   = (const float*)d_in[5];
    const float* wo   = (const float*)d_in[6];
    // d_in[7..9] (k_cache, v_cache, block_ids): scatter/gather is an identity.
    float* out = (float*)d_out;

    cudaFuncSetAttribute(qkv_mma_kernel,
                         cudaFuncAttributeMaxDynamicSharedMemorySize, GEMM_SMEM);
    cudaFuncSetAttribute(o_mma_kernel,
                         cudaFuncAttributeMaxDynamicSharedMemorySize, GEMM_SMEM);
    cudaFuncSetAttribute(flash_mma_kernel,
                         cudaFuncAttributeMaxDynamicSharedMemorySize, FLASH_SMEM);

    // 1) fp32 -> split-bf16 conversions (single merged launch)
    cvt_all_kernel<<<CVT_ALL_BLOCKS, 256>>>(hs, wq, wk, wv, wo);

    // 2) QKV projections on HMMA
    qkv_mma_kernel<<<dim3(48, 16), 256, GEMM_SMEM>>>();

    // 3) Fused RoPE + split-bf16 for Q/K, V split
    rope_split_kernel<<<(ROPE_TOTAL + 255) / 256, 256>>>(cosb, sinb);

    // 4) HMMA causal flash attention (writes split-bf16 AO directly)
    flash_mma_kernel<<<dim3(32, 32), 128, FLASH_SMEM>>>();

    // 5) O projection on HMMA
    o_mma_kernel<<<dim3(32, 16), 256, GEMM_SMEM>>>(out);
}